// round 4
// baseline (speedup 1.0000x reference)
#include <cuda_runtime.h>
#include <math.h>

#define DIM 64
#define MAXN 200000

// Scratch (allocation-free rule: __device__ globals). 102 MB total.
__device__ float g_bufA[(size_t)MAXN * DIM];
__device__ float g_bufB[(size_t)MAXN * DIM];
__device__ int   g_rowptr[MAXN + 1];

__device__ __forceinline__ float warpAllSum(float v) {
#pragma unroll
    for (int o = 16; o; o >>= 1) v += __shfl_xor_sync(0xffffffffu, v, o);
    return v;
}

// butterfly within a 16-lane half
__device__ __forceinline__ float halfAllSum(float v) {
#pragma unroll
    for (int o = 8; o; o >>= 1) v += __shfl_xor_sync(0xffffffffu, v, o);
    return v;
}

// ---------------------------------------------------------------------------
// logmap0: warp per node, lane handles dims [2l,2l+1].  weight -> bufA
// ---------------------------------------------------------------------------
__global__ void k_logmap(const float* __restrict__ w, int N) {
    int warp = (blockIdx.x * blockDim.x + threadIdx.x) >> 5;
    int lane = threadIdx.x & 31;
    if (warp >= N) return;
    const float2 v = __ldcs((const float2*)(w + (size_t)warp * DIM + lane * 2));
    float y0 = (lane == 0) ? 0.0f : v.x;
    float y1 = v.y;
    float n2 = warpAllSum(y0 * y0 + y1 * y1);
    float norm = fmaxf(sqrtf(n2), 1e-15f);
    float w0 = __shfl_sync(0xffffffffu, v.x, 0);
    float theta = fmaxf(w0, 1.0f + 1e-7f);
    float s = acoshf(theta) / norm;
    float2 o2;
    o2.x = (lane == 0) ? 0.0f : v.x * s;
    o2.y = v.y * s;
    *(float2*)(g_bufA + (size_t)warp * DIM + lane * 2) = o2;
}

// ---------------------------------------------------------------------------
// rowptr[r] = lower_bound(adj_row, r); rowptr[N] = E
// ---------------------------------------------------------------------------
__global__ void k_rowptr(const int* __restrict__ row, int E, int N) {
    int r = blockIdx.x * blockDim.x + threadIdx.x;
    if (r > N) return;
    int lo = 0, hi = E;
    while (lo < hi) {
        int m = (lo + hi) >> 1;
        if (__ldg(&row[m]) < r) lo = m + 1; else hi = m;
    }
    g_rowptr[r] = lo;
}

// ---------------------------------------------------------------------------
// SpMV dim-split pass: warp per row, half-warp per edge, float2 per lane
// covering dims [dimOff + 2q, dimOff + 2q + 1]. Edges via __ldcs (streaming).
// Unrolled: up to 4 gathers in flight per lane.
// srcIsB: 0 -> read bufA write bufB ; 1 -> read bufB write bufA
// ---------------------------------------------------------------------------
__global__ void k_spmv_pass(const float* __restrict__ vals, const int* __restrict__ col,
                            int N, int srcIsB, int dimOff) {
    int warp = (blockIdx.x * blockDim.x + threadIdx.x) >> 5;
    int lane = threadIdx.x & 31;
    if (warp >= N) return;
    int half = lane >> 4, q = lane & 15;
    const float* __restrict__ in  = (srcIsB ? g_bufB : g_bufA) + dimOff + q * 2;
    float* __restrict__ out       = srcIsB ? g_bufA : g_bufB;
    int s = g_rowptr[warp];
    int e = g_rowptr[warp + 1];

    float2 sum = make_float2(0.0f, 0.0f);
    int b = s;
    // 8 edges per iter: 4 per half -> 4 gathers in flight
    for (; b + 8 <= e; b += 8) {
        int k0 = b + half, k1 = b + half + 2, k2 = b + half + 4, k3 = b + half + 6;
        int   c0 = __ldcs(&col[k0]);
        int   c1 = __ldcs(&col[k1]);
        int   c2 = __ldcs(&col[k2]);
        int   c3 = __ldcs(&col[k3]);
        float v0 = __ldcs(&vals[k0]);
        float v1 = __ldcs(&vals[k1]);
        float v2 = __ldcs(&vals[k2]);
        float v3 = __ldcs(&vals[k3]);
        float2 x0 = *(const float2*)(in + (size_t)c0 * DIM);
        float2 x1 = *(const float2*)(in + (size_t)c1 * DIM);
        float2 x2 = *(const float2*)(in + (size_t)c2 * DIM);
        float2 x3 = *(const float2*)(in + (size_t)c3 * DIM);
        sum.x = fmaf(v0, x0.x, sum.x); sum.y = fmaf(v0, x0.y, sum.y);
        sum.x = fmaf(v1, x1.x, sum.x); sum.y = fmaf(v1, x1.y, sum.y);
        sum.x = fmaf(v2, x2.x, sum.x); sum.y = fmaf(v2, x2.y, sum.y);
        sum.x = fmaf(v3, x3.x, sum.x); sum.y = fmaf(v3, x3.y, sum.y);
    }
    for (; b + 4 <= e; b += 4) {
        int k0 = b + half, k1 = b + half + 2;
        int   c0 = __ldcs(&col[k0]);
        int   c1 = __ldcs(&col[k1]);
        float v0 = __ldcs(&vals[k0]);
        float v1 = __ldcs(&vals[k1]);
        float2 x0 = *(const float2*)(in + (size_t)c0 * DIM);
        float2 x1 = *(const float2*)(in + (size_t)c1 * DIM);
        sum.x = fmaf(v0, x0.x, sum.x); sum.y = fmaf(v0, x0.y, sum.y);
        sum.x = fmaf(v1, x1.x, sum.x); sum.y = fmaf(v1, x1.y, sum.y);
    }
    for (; b < e; b += 2) {
        int k = b + half;
        if (k < e) {
            int   c = __ldcs(&col[k]);
            float v = __ldcs(&vals[k]);
            float2 x = *(const float2*)(in + (size_t)c * DIM);
            sum.x = fmaf(v, x.x, sum.x); sum.y = fmaf(v, x.y, sum.y);
        }
    }
    // combine halves
    sum.x += __shfl_xor_sync(0xffffffffu, sum.x, 16);
    sum.y += __shfl_xor_sync(0xffffffffu, sum.y, 16);
    if (half == 0)
        *(float2*)(out + (size_t)warp * DIM + dimOff + q * 2) = sum;
}

// ---------------------------------------------------------------------------
// Fused layer 3 + expmap0 + proj (warp per row, full 64 dims):
//   h3 = A*h2 (gather bufA, resident); acc = (h1+h2)+h3; -> bufB[row]
// ---------------------------------------------------------------------------
__global__ void k_spmv3_final(const float* __restrict__ vals, const int* __restrict__ col,
                              int N) {
    int warp = (blockIdx.x * blockDim.x + threadIdx.x) >> 5;
    int lane = threadIdx.x & 31;
    if (warp >= N) return;
    int half = lane >> 4, q = lane & 15;
    int s = g_rowptr[warp];
    int e = g_rowptr[warp + 1];

    const float* __restrict__ in = g_bufA + q * 4;
    float4 h3 = make_float4(0.0f, 0.0f, 0.0f, 0.0f);
    int b = s;
    for (; b + 4 <= e; b += 4) {
        int k0 = b + half, k1 = b + half + 2;
        int   c0 = __ldcs(&col[k0]);
        int   c1 = __ldcs(&col[k1]);
        float v0 = __ldcs(&vals[k0]);
        float v1 = __ldcs(&vals[k1]);
        float4 x0 = *(const float4*)(in + (size_t)c0 * DIM);
        float4 x1 = *(const float4*)(in + (size_t)c1 * DIM);
        h3.x = fmaf(v0, x0.x, h3.x); h3.y = fmaf(v0, x0.y, h3.y);
        h3.z = fmaf(v0, x0.z, h3.z); h3.w = fmaf(v0, x0.w, h3.w);
        h3.x = fmaf(v1, x1.x, h3.x); h3.y = fmaf(v1, x1.y, h3.y);
        h3.z = fmaf(v1, x1.z, h3.z); h3.w = fmaf(v1, x1.w, h3.w);
    }
    for (; b < e; b += 2) {
        int k = b + half;
        if (k < e) {
            int   c = __ldcs(&col[k]);
            float v = __ldcs(&vals[k]);
            float4 x = *(const float4*)(in + (size_t)c * DIM);
            h3.x = fmaf(v, x.x, h3.x); h3.y = fmaf(v, x.y, h3.y);
            h3.z = fmaf(v, x.z, h3.z); h3.w = fmaf(v, x.w, h3.w);
        }
    }
    h3.x += __shfl_xor_sync(0xffffffffu, h3.x, 16);
    h3.y += __shfl_xor_sync(0xffffffffu, h3.y, 16);
    h3.z += __shfl_xor_sync(0xffffffffu, h3.z, 16);
    h3.w += __shfl_xor_sync(0xffffffffu, h3.w, 16);

    size_t off = (size_t)warp * DIM + q * 4;
    const float4 h1 = __ldcs((const float4*)(g_bufB + off));  // single use
    const float4 h2 = *(const float4*)(g_bufA + off);
    float ax = (h1.x + h2.x) + h3.x;
    float ay = (h1.y + h2.y) + h3.y;
    float az = (h1.z + h2.z) + h3.z;
    float aw = (h1.w + h2.w) + h3.w;

    float x0 = (q == 0) ? 0.0f : ax;   // dim0 = x of q==0
    float n2 = halfAllSum(x0 * x0 + ay * ay + az * az + aw * aw);
    float xn = fmaxf(sqrtf(n2), 1e-15f);
    float sc = sinhf(xn) / xn;
    float r0 = x0 * sc, r1 = ay * sc, r2 = az * sc, r3 = aw * sc;
    float rn2 = halfAllSum(r0 * r0 + r1 * r1 + r2 * r2 + r3 * r3);
    float first = sqrtf(1.0f + rn2);
    if (half == 0) {
        float4 o;
        o.x = (q == 0) ? first : r0;
        o.y = r1; o.z = r2; o.w = r3;
        *(float4*)(g_bufB + off) = o;
    }
}

__global__ void k_zero(float* out, int n) {
    int i = blockIdx.x * blockDim.x + threadIdx.x;
    if (i < n) out[i] = 0.0f;
}

// ---------------------------------------------------------------------------
// loss: one warp per training pair; reads final embeddings from bufB.
// ---------------------------------------------------------------------------
__global__ void k_loss(const int* __restrict__ anchor, const int* __restrict__ pos,
                       const int* __restrict__ neg, int M, int numNeg,
                       float* __restrict__ out) {
    int lane = threadIdx.x & 31;
    int wib  = threadIdx.x >> 5;
    int warp = blockIdx.x * (blockDim.x >> 5) + wib;
    __shared__ float partial[8];

    float contrib = 0.0f;
    if (warp < M) {
        const float* __restrict__ h = g_bufB;
        int ai = __ldcs(&anchor[warp]);
        int pi = __ldcs(&pos[warp]);
        float2 av = *(const float2*)(h + (size_t)ai * DIM + lane * 2);
        float2 pv = *(const float2*)(h + (size_t)pi * DIM + lane * 2);
        float dotap = warpAllSum(av.x * pv.x + av.y * pv.y);
        float a0 = __shfl_sync(0xffffffffu, av.x, 0);
        float p0 = __shfl_sync(0xffffffffu, pv.x, 0);
        float mink = dotap - 2.0f * a0 * p0;
        float th   = fmaxf(-mink, 1.0f + 1e-7f);
        float ac   = acoshf(th);
        float pos_score = fminf(ac * ac, 50.0f);

        float score = (1.0f - mink - a0 - p0) / (a0 * p0);
        float w = 1.0f / (1.0f + expf(score));   // sigmoid(-score)

        // hard negative: argmin_j ||h[neg_j] - p||^2 (first min kept)
        float best = 3.4e38f;
        float2 bv = make_float2(0.0f, 0.0f);
        if (numNeg == 16) {
#pragma unroll 4
            for (int j = 0; j < 16; j++) {
                int ni = __ldcs(&neg[(size_t)warp * 16 + j]);
                float2 nv = *(const float2*)(h + (size_t)ni * DIM + lane * 2);
                float dx = nv.x - pv.x, dy = nv.y - pv.y;
                float d = warpAllSum(dx * dx + dy * dy);
                if (d < best) { best = d; bv = nv; }
            }
        } else {
            for (int j = 0; j < numNeg; j++) {
                int ni = __ldcs(&neg[(size_t)warp * numNeg + j]);
                float2 nv = *(const float2*)(h + (size_t)ni * DIM + lane * 2);
                float dx = nv.x - pv.x, dy = nv.y - pv.y;
                float d = warpAllSum(dx * dx + dy * dy);
                if (d < best) { best = d; bv = nv; }
            }
        }
        float dotan = warpAllSum(av.x * bv.x + av.y * bv.y);
        float n0 = __shfl_sync(0xffffffffu, bv.x, 0);
        float minkn = dotan - 2.0f * a0 * n0;
        float thn = fmaxf(-minkn, 1.0f + 1e-7f);
        float acn = acoshf(thn);
        float neg_score = fminf(acn * acn, 50.0f);

        contrib = fmaxf(pos_score - neg_score + 0.1f * w, 0.0f);
    }
    if (lane == 0) partial[wib] = contrib;
    __syncthreads();
    if (threadIdx.x == 0) {
        float s = 0.0f;
#pragma unroll
        for (int i = 0; i < 8; i++) s += partial[i];
        atomicAdd(out, s);
    }
}

// ---------------------------------------------------------------------------
extern "C" void kernel_launch(void* const* d_in, const int* in_sizes, int n_in,
                              void* d_out, int out_size) {
    const float* weight   = (const float*)d_in[0];
    const float* adj_vals = (const float*)d_in[1];
    const int*   adj_row  = (const int*)d_in[2];
    const int*   adj_col  = (const int*)d_in[3];
    const int*   anchor   = (const int*)d_in[4];
    const int*   pos      = (const int*)d_in[5];
    const int*   neg      = (const int*)d_in[6];
    float* out = (float*)d_out;

    int N = in_sizes[0] / DIM;         // 200000
    int E = in_sizes[1];               // 1.6M
    int M = in_sizes[4];               // 65536
    int numNeg = (M > 0) ? in_sizes[6] / M : 16;

    const int TPB = 256;               // 8 warps per block
    int nodeBlocks = (N + 7) / 8;      // warp per node
    int rpBlocks   = (N + 1 + TPB - 1) / TPB;
    int lossBlocks = (M + 7) / 8;

    k_logmap<<<nodeBlocks, TPB>>>(weight, N);
    k_rowptr<<<rpBlocks, TPB>>>(adj_row, E, N);
    // layer 1: A(x_t) -> B(h1), two dim passes
    k_spmv_pass<<<nodeBlocks, TPB>>>(adj_vals, adj_col, N, 0, 0);
    k_spmv_pass<<<nodeBlocks, TPB>>>(adj_vals, adj_col, N, 0, 32);
    // layer 2: B(h1) -> A(h2), two dim passes
    k_spmv_pass<<<nodeBlocks, TPB>>>(adj_vals, adj_col, N, 1, 0);
    k_spmv_pass<<<nodeBlocks, TPB>>>(adj_vals, adj_col, N, 1, 32);
    // layer 3 fused with expmap/proj -> B(final h)
    k_spmv3_final<<<nodeBlocks, TPB>>>(adj_vals, adj_col, N);
    k_zero<<<(out_size + TPB - 1) / TPB, TPB>>>(out, out_size);
    k_loss<<<lossBlocks, TPB>>>(anchor, pos, neg, M, numNeg, out);
}

// round 5
// speedup vs baseline: 1.0833x; 1.0833x over previous
#include <cuda_runtime.h>
#include <math.h>

#define DIM 64
#define MAXN 200000

// Scratch (allocation-free rule: __device__ globals). 102 MB total.
__device__ float g_bufA[(size_t)MAXN * DIM];
__device__ float g_bufB[(size_t)MAXN * DIM];
__device__ int   g_rowptr[MAXN + 1];

__device__ __forceinline__ float warpAllSum(float v) {
#pragma unroll
    for (int o = 16; o; o >>= 1) v += __shfl_xor_sync(0xffffffffu, v, o);
    return v;
}

// butterfly within a 16-lane half
__device__ __forceinline__ float halfAllSum(float v) {
#pragma unroll
    for (int o = 8; o; o >>= 1) v += __shfl_xor_sync(0xffffffffu, v, o);
    return v;
}

// ---------------------------------------------------------------------------
// logmap0: warp per node, lane handles dims [2l,2l+1].  weight -> bufA
// ---------------------------------------------------------------------------
__global__ void k_logmap(const float* __restrict__ w, int N) {
    int warp = (blockIdx.x * blockDim.x + threadIdx.x) >> 5;
    int lane = threadIdx.x & 31;
    if (warp >= N) return;
    const float2 v = __ldcs((const float2*)(w + (size_t)warp * DIM + lane * 2));
    float y0 = (lane == 0) ? 0.0f : v.x;
    float y1 = v.y;
    float n2 = warpAllSum(y0 * y0 + y1 * y1);
    float norm = fmaxf(sqrtf(n2), 1e-15f);
    float w0 = __shfl_sync(0xffffffffu, v.x, 0);
    float theta = fmaxf(w0, 1.0f + 1e-7f);
    float s = acoshf(theta) / norm;
    float2 o2;
    o2.x = (lane == 0) ? 0.0f : v.x * s;
    o2.y = v.y * s;
    *(float2*)(g_bufA + (size_t)warp * DIM + lane * 2) = o2;
}

// ---------------------------------------------------------------------------
// rowptr[r] = lower_bound(adj_row, r); rowptr[N] = E
// ---------------------------------------------------------------------------
__global__ void k_rowptr(const int* __restrict__ row, int E, int N) {
    int r = blockIdx.x * blockDim.x + threadIdx.x;
    if (r > N) return;
    int lo = 0, hi = E;
    while (lo < hi) {
        int m = (lo + hi) >> 1;
        if (__ldg(&row[m]) < r) lo = m + 1; else hi = m;
    }
    g_rowptr[r] = lo;
}

// ---------------------------------------------------------------------------
// Row gather, half-warp per edge, float4 per lane (full 64 dims), unrolled to
// 4 edges in flight per half (8 edges/iter). Edge streams via __ldcs.
//   half = lane>>4 (0/1), q = lane&15 (dims [4q..4q+3])
// Returns per-half partial; caller combines halves via shfl 16.
// ---------------------------------------------------------------------------
__device__ __forceinline__ float4 row_gather4(const float* __restrict__ in,
                                              const float* __restrict__ vals,
                                              const int* __restrict__ col,
                                              int s, int e, int half) {
    float4 sum = make_float4(0.0f, 0.0f, 0.0f, 0.0f);
    int b = s;
    for (; b + 8 <= e; b += 8) {
        int k0 = b + half, k1 = k0 + 2, k2 = k0 + 4, k3 = k0 + 6;
        int   c0 = __ldcs(&col[k0]);
        int   c1 = __ldcs(&col[k1]);
        int   c2 = __ldcs(&col[k2]);
        int   c3 = __ldcs(&col[k3]);
        float v0 = __ldcs(&vals[k0]);
        float v1 = __ldcs(&vals[k1]);
        float v2 = __ldcs(&vals[k2]);
        float v3 = __ldcs(&vals[k3]);
        float4 x0 = *(const float4*)(in + (size_t)c0 * DIM);
        float4 x1 = *(const float4*)(in + (size_t)c1 * DIM);
        float4 x2 = *(const float4*)(in + (size_t)c2 * DIM);
        float4 x3 = *(const float4*)(in + (size_t)c3 * DIM);
        sum.x = fmaf(v0, x0.x, sum.x); sum.y = fmaf(v0, x0.y, sum.y);
        sum.z = fmaf(v0, x0.z, sum.z); sum.w = fmaf(v0, x0.w, sum.w);
        sum.x = fmaf(v1, x1.x, sum.x); sum.y = fmaf(v1, x1.y, sum.y);
        sum.z = fmaf(v1, x1.z, sum.z); sum.w = fmaf(v1, x1.w, sum.w);
        sum.x = fmaf(v2, x2.x, sum.x); sum.y = fmaf(v2, x2.y, sum.y);
        sum.z = fmaf(v2, x2.z, sum.z); sum.w = fmaf(v2, x2.w, sum.w);
        sum.x = fmaf(v3, x3.x, sum.x); sum.y = fmaf(v3, x3.y, sum.y);
        sum.z = fmaf(v3, x3.z, sum.z); sum.w = fmaf(v3, x3.w, sum.w);
    }
    for (; b + 4 <= e; b += 4) {
        int k0 = b + half, k1 = k0 + 2;
        int   c0 = __ldcs(&col[k0]);
        int   c1 = __ldcs(&col[k1]);
        float v0 = __ldcs(&vals[k0]);
        float v1 = __ldcs(&vals[k1]);
        float4 x0 = *(const float4*)(in + (size_t)c0 * DIM);
        float4 x1 = *(const float4*)(in + (size_t)c1 * DIM);
        sum.x = fmaf(v0, x0.x, sum.x); sum.y = fmaf(v0, x0.y, sum.y);
        sum.z = fmaf(v0, x0.z, sum.z); sum.w = fmaf(v0, x0.w, sum.w);
        sum.x = fmaf(v1, x1.x, sum.x); sum.y = fmaf(v1, x1.y, sum.y);
        sum.z = fmaf(v1, x1.z, sum.z); sum.w = fmaf(v1, x1.w, sum.w);
    }
    for (; b < e; b += 2) {
        int k = b + half;
        if (k < e) {
            int   c = __ldcs(&col[k]);
            float v = __ldcs(&vals[k]);
            float4 x = *(const float4*)(in + (size_t)c * DIM);
            sum.x = fmaf(v, x.x, sum.x); sum.y = fmaf(v, x.y, sum.y);
            sum.z = fmaf(v, x.z, sum.z); sum.w = fmaf(v, x.w, sum.w);
        }
    }
    return sum;
}

__device__ __forceinline__ void combineHalves(float4& s) {
    s.x += __shfl_xor_sync(0xffffffffu, s.x, 16);
    s.y += __shfl_xor_sync(0xffffffffu, s.y, 16);
    s.z += __shfl_xor_sync(0xffffffffu, s.z, 16);
    s.w += __shfl_xor_sync(0xffffffffu, s.w, 16);
}

// ---------------------------------------------------------------------------
// SpMV layers 1 & 2 (warp per row). Output stored streaming (__stcs) so the
// write-allocate traffic doesn't evict the resident gather set.
// srcIsB: 0 -> read bufA write bufB ; 1 -> read bufB write bufA
// ---------------------------------------------------------------------------
__global__ void k_spmv(const float* __restrict__ vals, const int* __restrict__ col,
                       int N, int srcIsB) {
    int warp = (blockIdx.x * blockDim.x + threadIdx.x) >> 5;
    int lane = threadIdx.x & 31;
    if (warp >= N) return;
    int half = lane >> 4, q = lane & 15;
    const float* __restrict__ in  = (srcIsB ? g_bufB : g_bufA) + q * 4;
    float* __restrict__ out       = srcIsB ? g_bufA : g_bufB;
    int s = __ldg(&g_rowptr[warp]);
    int e = __ldg(&g_rowptr[warp + 1]);
    float4 sum = row_gather4(in, vals, col, s, e, half);
    combineHalves(sum);
    if (half == 0)
        __stcs((float4*)(out + (size_t)warp * DIM + q * 4), sum);
}

// ---------------------------------------------------------------------------
// Fused layer 3 + expmap0 + proj (warp per row):
//   h3 = A*h2 (gather bufA); acc = (h1+h2)+h3 (h1=bufB streamed, h2=bufA)
//   -> final embedding to bufB[row] (streamed store)
// ---------------------------------------------------------------------------
__global__ void k_spmv3_final(const float* __restrict__ vals, const int* __restrict__ col,
                              int N) {
    int warp = (blockIdx.x * blockDim.x + threadIdx.x) >> 5;
    int lane = threadIdx.x & 31;
    if (warp >= N) return;
    int half = lane >> 4, q = lane & 15;
    int s = __ldg(&g_rowptr[warp]);
    int e = __ldg(&g_rowptr[warp + 1]);

    float4 h3 = row_gather4(g_bufA + q * 4, vals, col, s, e, half);
    combineHalves(h3);   // both halves hold identical row sums

    size_t off = (size_t)warp * DIM + q * 4;
    const float4 h1 = __ldcs((const float4*)(g_bufB + off));  // single use
    const float4 h2 = *(const float4*)(g_bufA + off);
    float ax = (h1.x + h2.x) + h3.x;
    float ay = (h1.y + h2.y) + h3.y;
    float az = (h1.z + h2.z) + h3.z;
    float aw = (h1.w + h2.w) + h3.w;

    float x0 = (q == 0) ? 0.0f : ax;   // dim0 = x of q==0
    float n2 = halfAllSum(x0 * x0 + ay * ay + az * az + aw * aw);
    float xn = fmaxf(sqrtf(n2), 1e-15f);
    float sc = sinhf(xn) / xn;
    float r0 = x0 * sc, r1 = ay * sc, r2 = az * sc, r3 = aw * sc;
    float rn2 = halfAllSum(r0 * r0 + r1 * r1 + r2 * r2 + r3 * r3);
    float first = sqrtf(1.0f + rn2);
    if (half == 0) {
        float4 o;
        o.x = (q == 0) ? first : r0;
        o.y = r1; o.z = r2; o.w = r3;
        __stcs((float4*)(g_bufB + off), o);
    }
}

__global__ void k_zero(float* out, int n) {
    int i = blockIdx.x * blockDim.x + threadIdx.x;
    if (i < n) out[i] = 0.0f;
}

// ---------------------------------------------------------------------------
// loss: one warp per training pair; reads final embeddings from bufB.
// ---------------------------------------------------------------------------
__global__ void k_loss(const int* __restrict__ anchor, const int* __restrict__ pos,
                       const int* __restrict__ neg, int M, int numNeg,
                       float* __restrict__ out) {
    int lane = threadIdx.x & 31;
    int wib  = threadIdx.x >> 5;
    int warp = blockIdx.x * (blockDim.x >> 5) + wib;
    __shared__ float partial[8];

    float contrib = 0.0f;
    if (warp < M) {
        const float* __restrict__ h = g_bufB;
        int ai = __ldcs(&anchor[warp]);
        int pi = __ldcs(&pos[warp]);
        float2 av = *(const float2*)(h + (size_t)ai * DIM + lane * 2);
        float2 pv = *(const float2*)(h + (size_t)pi * DIM + lane * 2);
        float dotap = warpAllSum(av.x * pv.x + av.y * pv.y);
        float a0 = __shfl_sync(0xffffffffu, av.x, 0);
        float p0 = __shfl_sync(0xffffffffu, pv.x, 0);
        float mink = dotap - 2.0f * a0 * p0;
        float th   = fmaxf(-mink, 1.0f + 1e-7f);
        float ac   = acoshf(th);
        float pos_score = fminf(ac * ac, 50.0f);

        float score = (1.0f - mink - a0 - p0) / (a0 * p0);
        float w = 1.0f / (1.0f + expf(score));   // sigmoid(-score)

        // hard negative: argmin_j ||h[neg_j] - p||^2 (first min kept)
        float best = 3.4e38f;
        float2 bv = make_float2(0.0f, 0.0f);
        if (numNeg == 16) {
#pragma unroll 4
            for (int j = 0; j < 16; j++) {
                int ni = __ldcs(&neg[(size_t)warp * 16 + j]);
                float2 nv = *(const float2*)(h + (size_t)ni * DIM + lane * 2);
                float dx = nv.x - pv.x, dy = nv.y - pv.y;
                float d = warpAllSum(dx * dx + dy * dy);
                if (d < best) { best = d; bv = nv; }
            }
        } else {
            for (int j = 0; j < numNeg; j++) {
                int ni = __ldcs(&neg[(size_t)warp * numNeg + j]);
                float2 nv = *(const float2*)(h + (size_t)ni * DIM + lane * 2);
                float dx = nv.x - pv.x, dy = nv.y - pv.y;
                float d = warpAllSum(dx * dx + dy * dy);
                if (d < best) { best = d; bv = nv; }
            }
        }
        float dotan = warpAllSum(av.x * bv.x + av.y * bv.y);
        float n0 = __shfl_sync(0xffffffffu, bv.x, 0);
        float minkn = dotan - 2.0f * a0 * n0;
        float thn = fmaxf(-minkn, 1.0f + 1e-7f);
        float acn = acoshf(thn);
        float neg_score = fminf(acn * acn, 50.0f);

        contrib = fmaxf(pos_score - neg_score + 0.1f * w, 0.0f);
    }
    if (lane == 0) partial[wib] = contrib;
    __syncthreads();
    if (threadIdx.x == 0) {
        float s = 0.0f;
#pragma unroll
        for (int i = 0; i < 8; i++) s += partial[i];
        atomicAdd(out, s);
    }
}

// ---------------------------------------------------------------------------
extern "C" void kernel_launch(void* const* d_in, const int* in_sizes, int n_in,
                              void* d_out, int out_size) {
    const float* weight   = (const float*)d_in[0];
    const float* adj_vals = (const float*)d_in[1];
    const int*   adj_row  = (const int*)d_in[2];
    const int*   adj_col  = (const int*)d_in[3];
    const int*   anchor   = (const int*)d_in[4];
    const int*   pos      = (const int*)d_in[5];
    const int*   neg      = (const int*)d_in[6];
    float* out = (float*)d_out;

    int N = in_sizes[0] / DIM;         // 200000
    int E = in_sizes[1];               // 1.6M
    int M = in_sizes[4];               // 65536
    int numNeg = (M > 0) ? in_sizes[6] / M : 16;

    const int TPB = 256;               // 8 warps per block
    int nodeBlocks = (N + 7) / 8;      // warp per node
    int rpBlocks   = (N + 1 + TPB - 1) / TPB;
    int lossBlocks = (M + 7) / 8;

    k_logmap<<<nodeBlocks, TPB>>>(weight, N);
    k_rowptr<<<rpBlocks, TPB>>>(adj_row, E, N);
    k_spmv<<<nodeBlocks, TPB>>>(adj_vals, adj_col, N, /*srcIsB=*/0); // A(x_t) -> B(h1)
    k_spmv<<<nodeBlocks, TPB>>>(adj_vals, adj_col, N, /*srcIsB=*/1); // B(h1) -> A(h2)
    k_spmv3_final<<<nodeBlocks, TPB>>>(adj_vals, adj_col, N);        // -> B(final h)
    k_zero<<<(out_size + TPB - 1) / TPB, TPB>>>(out, out_size);
    k_loss<<<lossBlocks, TPB>>>(anchor, pos, neg, M, numNeg, out);
}

// round 6
// speedup vs baseline: 1.3499x; 1.2461x over previous
#include <cuda_runtime.h>
#include <math.h>

#define DIM 64
#define MAXN 200000

// Scratch (allocation-free rule: __device__ globals). 102 MB total.
__device__ float g_bufA[(size_t)MAXN * DIM];
__device__ float g_bufB[(size_t)MAXN * DIM];
__device__ int   g_rowptr[MAXN + 1];

__device__ __forceinline__ float warpAllSum(float v) {
#pragma unroll
    for (int o = 16; o; o >>= 1) v += __shfl_xor_sync(0xffffffffu, v, o);
    return v;
}

// butterfly within a 16-lane half (offsets 8,4,2,1 stay inside the half)
__device__ __forceinline__ float halfAllSum(float v) {
#pragma unroll
    for (int o = 8; o; o >>= 1) v += __shfl_xor_sync(0xffffffffu, v, o);
    return v;
}

// ---------------------------------------------------------------------------
// logmap0: warp per node, lane handles dims [2l,2l+1].  weight -> bufA
// ---------------------------------------------------------------------------
__global__ void k_logmap(const float* __restrict__ w, int N) {
    int warp = (blockIdx.x * blockDim.x + threadIdx.x) >> 5;
    int lane = threadIdx.x & 31;
    if (warp >= N) return;
    const float2 v = *(const float2*)(w + (size_t)warp * DIM + lane * 2);
    float y0 = (lane == 0) ? 0.0f : v.x;
    float y1 = v.y;
    float n2 = warpAllSum(y0 * y0 + y1 * y1);
    float norm = fmaxf(sqrtf(n2), 1e-15f);
    float w0 = __shfl_sync(0xffffffffu, v.x, 0);
    float theta = fmaxf(w0, 1.0f + 1e-7f);
    float s = acoshf(theta) / norm;
    float2 o2;
    o2.x = (lane == 0) ? 0.0f : v.x * s;
    o2.y = v.y * s;
    *(float2*)(g_bufA + (size_t)warp * DIM + lane * 2) = o2;
}

// ---------------------------------------------------------------------------
// rowptr[r] = lower_bound(adj_row, r); rowptr[N] = E
// ---------------------------------------------------------------------------
__global__ void k_rowptr(const int* __restrict__ row, int E, int N) {
    int r = blockIdx.x * blockDim.x + threadIdx.x;
    if (r > N) return;
    int lo = 0, hi = E;
    while (lo < hi) {
        int m = (lo + hi) >> 1;
        if (__ldg(&row[m]) < r) lo = m + 1; else hi = m;
    }
    g_rowptr[r] = lo;
}

// ---------------------------------------------------------------------------
// Row gather, HALF-WARP PER ROW, lane owns dims [4q..4q+3]. No reduction.
// 2-edge unroll -> 2 gathers in flight per half; one LDG serves both halves.
// s,e are per-half (uniform within the 16 lanes of a half).
// ---------------------------------------------------------------------------
__device__ __forceinline__ float4 half_row_gather(const float* __restrict__ in,
                                                  const float* __restrict__ vals,
                                                  const int* __restrict__ col,
                                                  int s, int e) {
    float4 sum = make_float4(0.0f, 0.0f, 0.0f, 0.0f);
    int k = s;
    for (; k + 2 <= e; k += 2) {
        int   c0 = __ldg(&col[k]);
        int   c1 = __ldg(&col[k + 1]);
        float v0 = __ldg(&vals[k]);
        float v1 = __ldg(&vals[k + 1]);
        float4 x0 = *(const float4*)(in + (size_t)c0 * DIM);
        float4 x1 = *(const float4*)(in + (size_t)c1 * DIM);
        sum.x = fmaf(v0, x0.x, sum.x); sum.y = fmaf(v0, x0.y, sum.y);
        sum.z = fmaf(v0, x0.z, sum.z); sum.w = fmaf(v0, x0.w, sum.w);
        sum.x = fmaf(v1, x1.x, sum.x); sum.y = fmaf(v1, x1.y, sum.y);
        sum.z = fmaf(v1, x1.z, sum.z); sum.w = fmaf(v1, x1.w, sum.w);
    }
    if (k < e) {
        int   c = __ldg(&col[k]);
        float v = __ldg(&vals[k]);
        float4 x = *(const float4*)(in + (size_t)c * DIM);
        sum.x = fmaf(v, x.x, sum.x); sum.y = fmaf(v, x.y, sum.y);
        sum.z = fmaf(v, x.z, sum.z); sum.w = fmaf(v, x.w, sum.w);
    }
    return sum;
}

// ---------------------------------------------------------------------------
// SpMV layers 1 & 2: warp handles rows {2w, 2w+1} (one per half).
// srcIsB: 0 -> read bufA write bufB ; 1 -> read bufB write bufA
// ---------------------------------------------------------------------------
__global__ void k_spmv(const float* __restrict__ vals, const int* __restrict__ col,
                       int N, int srcIsB) {
    int warp = (blockIdx.x * blockDim.x + threadIdx.x) >> 5;
    int lane = threadIdx.x & 31;
    int half = lane >> 4, q = lane & 15;
    int row = warp * 2 + half;
    bool valid = row < N;
    int rc = valid ? row : (N - 1);
    const float* __restrict__ in = (srcIsB ? g_bufB : g_bufA) + q * 4;
    float* __restrict__ out      = srcIsB ? g_bufA : g_bufB;
    int s = __ldg(&g_rowptr[rc]);
    int e = valid ? __ldg(&g_rowptr[rc + 1]) : s;
    float4 sum = half_row_gather(in, vals, col, s, e);
    if (valid)
        *(float4*)(out + (size_t)rc * DIM + q * 4) = sum;
}

// ---------------------------------------------------------------------------
// Fused layer 3 + expmap0 + proj: warp handles rows {2w, 2w+1}.
//   h3 = A*h2 (gather bufA); acc = (h1+h2)+h3; final h -> bufB[row]
// ---------------------------------------------------------------------------
__global__ void k_spmv3_final(const float* __restrict__ vals, const int* __restrict__ col,
                              int N) {
    int warp = (blockIdx.x * blockDim.x + threadIdx.x) >> 5;
    int lane = threadIdx.x & 31;
    int half = lane >> 4, q = lane & 15;
    int row = warp * 2 + half;
    bool valid = row < N;
    int rc = valid ? row : (N - 1);
    int s = __ldg(&g_rowptr[rc]);
    int e = valid ? __ldg(&g_rowptr[rc + 1]) : s;

    float4 h3 = half_row_gather(g_bufA + q * 4, vals, col, s, e);

    size_t off = (size_t)rc * DIM + q * 4;
    const float4 h1 = *(const float4*)(g_bufB + off);
    const float4 h2 = *(const float4*)(g_bufA + off);
    float ax = (h1.x + h2.x) + h3.x;
    float ay = (h1.y + h2.y) + h3.y;
    float az = (h1.z + h2.z) + h3.z;
    float aw = (h1.w + h2.w) + h3.w;

    float x0 = (q == 0) ? 0.0f : ax;   // dim0 = x of q==0
    float n2 = halfAllSum(x0 * x0 + ay * ay + az * az + aw * aw);
    float xn = fmaxf(sqrtf(n2), 1e-15f);
    float sc = sinhf(xn) / xn;
    float r0 = x0 * sc, r1 = ay * sc, r2 = az * sc, r3 = aw * sc;
    float rn2 = halfAllSum(r0 * r0 + r1 * r1 + r2 * r2 + r3 * r3);
    float first = sqrtf(1.0f + rn2);
    if (valid) {
        float4 o;
        o.x = (q == 0) ? first : r0;
        o.y = r1; o.z = r2; o.w = r3;
        *(float4*)(g_bufB + off) = o;
    }
}

__global__ void k_zero(float* out, int n) {
    int i = blockIdx.x * blockDim.x + threadIdx.x;
    if (i < n) out[i] = 0.0f;
}

// ---------------------------------------------------------------------------
// loss: one warp per training pair; reads final embeddings from bufB.
// ---------------------------------------------------------------------------
__global__ void k_loss(const int* __restrict__ anchor, const int* __restrict__ pos,
                       const int* __restrict__ neg, int M, int numNeg,
                       float* __restrict__ out) {
    int lane = threadIdx.x & 31;
    int wib  = threadIdx.x >> 5;
    int warp = blockIdx.x * (blockDim.x >> 5) + wib;
    __shared__ float partial[8];

    float contrib = 0.0f;
    if (warp < M) {
        const float* __restrict__ h = g_bufB;
        int ai = __ldg(&anchor[warp]);
        int pi = __ldg(&pos[warp]);
        float2 av = *(const float2*)(h + (size_t)ai * DIM + lane * 2);
        float2 pv = *(const float2*)(h + (size_t)pi * DIM + lane * 2);
        float dotap = warpAllSum(av.x * pv.x + av.y * pv.y);
        float a0 = __shfl_sync(0xffffffffu, av.x, 0);
        float p0 = __shfl_sync(0xffffffffu, pv.x, 0);
        float mink = dotap - 2.0f * a0 * p0;
        float th   = fmaxf(-mink, 1.0f + 1e-7f);
        float ac   = acoshf(th);
        float pos_score = fminf(ac * ac, 50.0f);

        float score = (1.0f - mink - a0 - p0) / (a0 * p0);
        float w = 1.0f / (1.0f + expf(score));   // sigmoid(-score)

        // hard negative: argmin_j ||h[neg_j] - p||^2 (first min kept)
        float best = 3.4e38f;
        float2 bv = make_float2(0.0f, 0.0f);
        if (numNeg == 16) {
#pragma unroll 4
            for (int j = 0; j < 16; j++) {
                int ni = __ldg(&neg[(size_t)warp * 16 + j]);
                float2 nv = *(const float2*)(h + (size_t)ni * DIM + lane * 2);
                float dx = nv.x - pv.x, dy = nv.y - pv.y;
                float d = warpAllSum(dx * dx + dy * dy);
                if (d < best) { best = d; bv = nv; }
            }
        } else {
            for (int j = 0; j < numNeg; j++) {
                int ni = __ldg(&neg[(size_t)warp * numNeg + j]);
                float2 nv = *(const float2*)(h + (size_t)ni * DIM + lane * 2);
                float dx = nv.x - pv.x, dy = nv.y - pv.y;
                float d = warpAllSum(dx * dx + dy * dy);
                if (d < best) { best = d; bv = nv; }
            }
        }
        float dotan = warpAllSum(av.x * bv.x + av.y * bv.y);
        float n0 = __shfl_sync(0xffffffffu, bv.x, 0);
        float minkn = dotan - 2.0f * a0 * n0;
        float thn = fmaxf(-minkn, 1.0f + 1e-7f);
        float acn = acoshf(thn);
        float neg_score = fminf(acn * acn, 50.0f);

        contrib = fmaxf(pos_score - neg_score + 0.1f * w, 0.0f);
    }
    if (lane == 0) partial[wib] = contrib;
    __syncthreads();
    if (threadIdx.x == 0) {
        float s = 0.0f;
#pragma unroll
        for (int i = 0; i < 8; i++) s += partial[i];
        atomicAdd(out, s);
    }
}

// ---------------------------------------------------------------------------
extern "C" void kernel_launch(void* const* d_in, const int* in_sizes, int n_in,
                              void* d_out, int out_size) {
    const float* weight   = (const float*)d_in[0];
    const float* adj_vals = (const float*)d_in[1];
    const int*   adj_row  = (const int*)d_in[2];
    const int*   adj_col  = (const int*)d_in[3];
    const int*   anchor   = (const int*)d_in[4];
    const int*   pos      = (const int*)d_in[5];
    const int*   neg      = (const int*)d_in[6];
    float* out = (float*)d_out;

    int N = in_sizes[0] / DIM;         // 200000
    int E = in_sizes[1];               // 1.6M
    int M = in_sizes[4];               // 65536
    int numNeg = (M > 0) ? in_sizes[6] / M : 16;

    const int TPB = 256;               // 8 warps per block
    int logBlocks  = (N + 7) / 8;              // warp per node
    int spmvWarps  = (N + 1) / 2;              // warp per 2 rows
    int spmvBlocks = (spmvWarps + 7) / 8;
    int rpBlocks   = (N + 1 + TPB - 1) / TPB;
    int lossBlocks = (M + 7) / 8;

    k_logmap<<<logBlocks, TPB>>>(weight, N);
    k_rowptr<<<rpBlocks, TPB>>>(adj_row, E, N);
    k_spmv<<<spmvBlocks, TPB>>>(adj_vals, adj_col, N, /*srcIsB=*/0); // A(x_t) -> B(h1)
    k_spmv<<<spmvBlocks, TPB>>>(adj_vals, adj_col, N, /*srcIsB=*/1); // B(h1) -> A(h2)
    k_spmv3_final<<<spmvBlocks, TPB>>>(adj_vals, adj_col, N);        // -> B(final h)
    k_zero<<<(out_size + TPB - 1) / TPB, TPB>>>(out, out_size);
    k_loss<<<lossBlocks, TPB>>>(anchor, pos, neg, M, numNeg, out);
}

// round 7
// speedup vs baseline: 1.3515x; 1.0012x over previous
#include <cuda_runtime.h>
#include <math.h>

#define DIM 64
#define MAXN 200000

// Scratch (allocation-free rule: __device__ globals). 102 MB total.
__device__ float g_bufA[(size_t)MAXN * DIM];
__device__ float g_bufB[(size_t)MAXN * DIM];
__device__ int   g_rowptr[MAXN + 1];

__device__ __forceinline__ float warpAllSum(float v) {
#pragma unroll
    for (int o = 16; o; o >>= 1) v += __shfl_xor_sync(0xffffffffu, v, o);
    return v;
}

// butterfly within a 16-lane half (offsets 8,4,2,1 stay inside the half)
__device__ __forceinline__ float halfAllSum(float v) {
#pragma unroll
    for (int o = 8; o; o >>= 1) v += __shfl_xor_sync(0xffffffffu, v, o);
    return v;
}

// ---------------------------------------------------------------------------
// logmap0: warp per node, lane handles dims [2l,2l+1].  weight -> bufA
// ---------------------------------------------------------------------------
__global__ void k_logmap(const float* __restrict__ w, int N) {
    int warp = (blockIdx.x * blockDim.x + threadIdx.x) >> 5;
    int lane = threadIdx.x & 31;
    if (warp >= N) return;
    const float2 v = *(const float2*)(w + (size_t)warp * DIM + lane * 2);
    float y0 = (lane == 0) ? 0.0f : v.x;
    float y1 = v.y;
    float n2 = warpAllSum(y0 * y0 + y1 * y1);
    float norm = fmaxf(sqrtf(n2), 1e-15f);
    float w0 = __shfl_sync(0xffffffffu, v.x, 0);
    float theta = fmaxf(w0, 1.0f + 1e-7f);
    float s = acoshf(theta) / norm;
    float2 o2;
    o2.x = (lane == 0) ? 0.0f : v.x * s;
    o2.y = v.y * s;
    *(float2*)(g_bufA + (size_t)warp * DIM + lane * 2) = o2;
}

// ---------------------------------------------------------------------------
// rowptr[r] = lower_bound(adj_row, r); rowptr[N] = E
// ---------------------------------------------------------------------------
__global__ void k_rowptr(const int* __restrict__ row, int E, int N) {
    int r = blockIdx.x * blockDim.x + threadIdx.x;
    if (r > N) return;
    int lo = 0, hi = E;
    while (lo < hi) {
        int m = (lo + hi) >> 1;
        if (__ldg(&row[m]) < r) lo = m + 1; else hi = m;
    }
    g_rowptr[r] = lo;
}

// ---------------------------------------------------------------------------
// Row gather, HALF-WARP PER ROW, lane owns dims [4q..4q+3]. No reduction.
// Chunk-4 batched prefetch: 8 independent col/vals loads, then 4 independent
// gathers in flight, then 16 FMAs. Breaks the col->gather dependent chain.
// ---------------------------------------------------------------------------
__device__ __forceinline__ float4 half_row_gather(const float* __restrict__ in,
                                                  const float* __restrict__ vals,
                                                  const int* __restrict__ col,
                                                  int s, int e) {
    float4 sum = make_float4(0.0f, 0.0f, 0.0f, 0.0f);
    int k = s;
    for (; k + 4 <= e; k += 4) {
        int   c0 = __ldg(&col[k]);
        int   c1 = __ldg(&col[k + 1]);
        int   c2 = __ldg(&col[k + 2]);
        int   c3 = __ldg(&col[k + 3]);
        float v0 = __ldg(&vals[k]);
        float v1 = __ldg(&vals[k + 1]);
        float v2 = __ldg(&vals[k + 2]);
        float v3 = __ldg(&vals[k + 3]);
        float4 x0 = *(const float4*)(in + (size_t)c0 * DIM);
        float4 x1 = *(const float4*)(in + (size_t)c1 * DIM);
        float4 x2 = *(const float4*)(in + (size_t)c2 * DIM);
        float4 x3 = *(const float4*)(in + (size_t)c3 * DIM);
        sum.x = fmaf(v0, x0.x, sum.x); sum.y = fmaf(v0, x0.y, sum.y);
        sum.z = fmaf(v0, x0.z, sum.z); sum.w = fmaf(v0, x0.w, sum.w);
        sum.x = fmaf(v1, x1.x, sum.x); sum.y = fmaf(v1, x1.y, sum.y);
        sum.z = fmaf(v1, x1.z, sum.z); sum.w = fmaf(v1, x1.w, sum.w);
        sum.x = fmaf(v2, x2.x, sum.x); sum.y = fmaf(v2, x2.y, sum.y);
        sum.z = fmaf(v2, x2.z, sum.z); sum.w = fmaf(v2, x2.w, sum.w);
        sum.x = fmaf(v3, x3.x, sum.x); sum.y = fmaf(v3, x3.y, sum.y);
        sum.z = fmaf(v3, x3.z, sum.z); sum.w = fmaf(v3, x3.w, sum.w);
    }
    if (k + 2 <= e) {
        int   c0 = __ldg(&col[k]);
        int   c1 = __ldg(&col[k + 1]);
        float v0 = __ldg(&vals[k]);
        float v1 = __ldg(&vals[k + 1]);
        float4 x0 = *(const float4*)(in + (size_t)c0 * DIM);
        float4 x1 = *(const float4*)(in + (size_t)c1 * DIM);
        sum.x = fmaf(v0, x0.x, sum.x); sum.y = fmaf(v0, x0.y, sum.y);
        sum.z = fmaf(v0, x0.z, sum.z); sum.w = fmaf(v0, x0.w, sum.w);
        sum.x = fmaf(v1, x1.x, sum.x); sum.y = fmaf(v1, x1.y, sum.y);
        sum.z = fmaf(v1, x1.z, sum.z); sum.w = fmaf(v1, x1.w, sum.w);
        k += 2;
    }
    if (k < e) {
        int   c = __ldg(&col[k]);
        float v = __ldg(&vals[k]);
        float4 x = *(const float4*)(in + (size_t)c * DIM);
        sum.x = fmaf(v, x.x, sum.x); sum.y = fmaf(v, x.y, sum.y);
        sum.z = fmaf(v, x.z, sum.z); sum.w = fmaf(v, x.w, sum.w);
    }
    return sum;
}

// ---------------------------------------------------------------------------
// SpMV layers 1 & 2: warp handles rows {2w, 2w+1} (one per half).
// srcIsB: 0 -> read bufA write bufB ; 1 -> read bufB write bufA
// ---------------------------------------------------------------------------
__global__ void __launch_bounds__(256, 5)
k_spmv(const float* __restrict__ vals, const int* __restrict__ col,
       int N, int srcIsB) {
    int warp = (blockIdx.x * blockDim.x + threadIdx.x) >> 5;
    int lane = threadIdx.x & 31;
    int half = lane >> 4, q = lane & 15;
    int row = warp * 2 + half;
    bool valid = row < N;
    int rc = valid ? row : (N - 1);
    const float* __restrict__ in = (srcIsB ? g_bufB : g_bufA) + q * 4;
    float* __restrict__ out      = srcIsB ? g_bufA : g_bufB;
    int s = __ldg(&g_rowptr[rc]);
    int e = valid ? __ldg(&g_rowptr[rc + 1]) : s;
    float4 sum = half_row_gather(in, vals, col, s, e);
    if (valid)
        *(float4*)(out + (size_t)rc * DIM + q * 4) = sum;
}

// ---------------------------------------------------------------------------
// Fused layer 3 + expmap0 + proj: warp handles rows {2w, 2w+1}.
//   h3 = A*h2 (gather bufA); acc = (h1+h2)+h3; final h -> bufB[row]
// ---------------------------------------------------------------------------
__global__ void __launch_bounds__(256, 5)
k_spmv3_final(const float* __restrict__ vals, const int* __restrict__ col, int N) {
    int warp = (blockIdx.x * blockDim.x + threadIdx.x) >> 5;
    int lane = threadIdx.x & 31;
    int half = lane >> 4, q = lane & 15;
    int row = warp * 2 + half;
    bool valid = row < N;
    int rc = valid ? row : (N - 1);
    int s = __ldg(&g_rowptr[rc]);
    int e = valid ? __ldg(&g_rowptr[rc + 1]) : s;

    float4 h3 = half_row_gather(g_bufA + q * 4, vals, col, s, e);

    size_t off = (size_t)rc * DIM + q * 4;
    const float4 h1 = *(const float4*)(g_bufB + off);
    const float4 h2 = *(const float4*)(g_bufA + off);
    float ax = (h1.x + h2.x) + h3.x;
    float ay = (h1.y + h2.y) + h3.y;
    float az = (h1.z + h2.z) + h3.z;
    float aw = (h1.w + h2.w) + h3.w;

    float x0 = (q == 0) ? 0.0f : ax;   // dim0 = x of q==0
    float n2 = halfAllSum(x0 * x0 + ay * ay + az * az + aw * aw);
    float xn = fmaxf(sqrtf(n2), 1e-15f);
    float sc = sinhf(xn) / xn;
    float r0 = x0 * sc, r1 = ay * sc, r2 = az * sc, r3 = aw * sc;
    float rn2 = halfAllSum(r0 * r0 + r1 * r1 + r2 * r2 + r3 * r3);
    float first = sqrtf(1.0f + rn2);
    if (valid) {
        float4 o;
        o.x = (q == 0) ? first : r0;
        o.y = r1; o.z = r2; o.w = r3;
        *(float4*)(g_bufB + off) = o;
    }
}

__global__ void k_zero(float* out, int n) {
    int i = blockIdx.x * blockDim.x + threadIdx.x;
    if (i < n) out[i] = 0.0f;
}

// ---------------------------------------------------------------------------
// loss: one warp per training pair; reads final embeddings from bufB.
// ---------------------------------------------------------------------------
__global__ void k_loss(const int* __restrict__ anchor, const int* __restrict__ pos,
                       const int* __restrict__ neg, int M, int numNeg,
                       float* __restrict__ out) {
    int lane = threadIdx.x & 31;
    int wib  = threadIdx.x >> 5;
    int warp = blockIdx.x * (blockDim.x >> 5) + wib;
    __shared__ float partial[8];

    float contrib = 0.0f;
    if (warp < M) {
        const float* __restrict__ h = g_bufB;
        int ai = __ldg(&anchor[warp]);
        int pi = __ldg(&pos[warp]);
        float2 av = *(const float2*)(h + (size_t)ai * DIM + lane * 2);
        float2 pv = *(const float2*)(h + (size_t)pi * DIM + lane * 2);
        float dotap = warpAllSum(av.x * pv.x + av.y * pv.y);
        float a0 = __shfl_sync(0xffffffffu, av.x, 0);
        float p0 = __shfl_sync(0xffffffffu, pv.x, 0);
        float mink = dotap - 2.0f * a0 * p0;
        float th   = fmaxf(-mink, 1.0f + 1e-7f);
        float ac   = acoshf(th);
        float pos_score = fminf(ac * ac, 50.0f);

        float score = (1.0f - mink - a0 - p0) / (a0 * p0);
        float w = 1.0f / (1.0f + expf(score));   // sigmoid(-score)

        // hard negative: argmin_j ||h[neg_j] - p||^2 (first min kept)
        float best = 3.4e38f;
        float2 bv = make_float2(0.0f, 0.0f);
        if (numNeg == 16) {
#pragma unroll 4
            for (int j = 0; j < 16; j++) {
                int ni = __ldg(&neg[(size_t)warp * 16 + j]);
                float2 nv = *(const float2*)(h + (size_t)ni * DIM + lane * 2);
                float dx = nv.x - pv.x, dy = nv.y - pv.y;
                float d = warpAllSum(dx * dx + dy * dy);
                if (d < best) { best = d; bv = nv; }
            }
        } else {
            for (int j = 0; j < numNeg; j++) {
                int ni = __ldg(&neg[(size_t)warp * numNeg + j]);
                float2 nv = *(const float2*)(h + (size_t)ni * DIM + lane * 2);
                float dx = nv.x - pv.x, dy = nv.y - pv.y;
                float d = warpAllSum(dx * dx + dy * dy);
                if (d < best) { best = d; bv = nv; }
            }
        }
        float dotan = warpAllSum(av.x * bv.x + av.y * bv.y);
        float n0 = __shfl_sync(0xffffffffu, bv.x, 0);
        float minkn = dotan - 2.0f * a0 * n0;
        float thn = fmaxf(-minkn, 1.0f + 1e-7f);
        float acn = acoshf(thn);
        float neg_score = fminf(acn * acn, 50.0f);

        contrib = fmaxf(pos_score - neg_score + 0.1f * w, 0.0f);
    }
    if (lane == 0) partial[wib] = contrib;
    __syncthreads();
    if (threadIdx.x == 0) {
        float s = 0.0f;
#pragma unroll
        for (int i = 0; i < 8; i++) s += partial[i];
        atomicAdd(out, s);
    }
}

// ---------------------------------------------------------------------------
extern "C" void kernel_launch(void* const* d_in, const int* in_sizes, int n_in,
                              void* d_out, int out_size) {
    const float* weight   = (const float*)d_in[0];
    const float* adj_vals = (const float*)d_in[1];
    const int*   adj_row  = (const int*)d_in[2];
    const int*   adj_col  = (const int*)d_in[3];
    const int*   anchor   = (const int*)d_in[4];
    const int*   pos      = (const int*)d_in[5];
    const int*   neg      = (const int*)d_in[6];
    float* out = (float*)d_out;

    int N = in_sizes[0] / DIM;         // 200000
    int E = in_sizes[1];               // 1.6M
    int M = in_sizes[4];               // 65536
    int numNeg = (M > 0) ? in_sizes[6] / M : 16;

    const int TPB = 256;               // 8 warps per block
    int logBlocks  = (N + 7) / 8;              // warp per node
    int spmvWarps  = (N + 1) / 2;              // warp per 2 rows
    int spmvBlocks = (spmvWarps + 7) / 8;
    int rpBlocks   = (N + 1 + TPB - 1) / TPB;
    int lossBlocks = (M + 7) / 8;

    k_logmap<<<logBlocks, TPB>>>(weight, N);
    k_rowptr<<<rpBlocks, TPB>>>(adj_row, E, N);
    k_spmv<<<spmvBlocks, TPB>>>(adj_vals, adj_col, N, /*srcIsB=*/0); // A(x_t) -> B(h1)
    k_spmv<<<spmvBlocks, TPB>>>(adj_vals, adj_col, N, /*srcIsB=*/1); // B(h1) -> A(h2)
    k_spmv3_final<<<spmvBlocks, TPB>>>(adj_vals, adj_col, N);        // -> B(final h)
    k_zero<<<(out_size + TPB - 1) / TPB, TPB>>>(out, out_size);
    k_loss<<<lossBlocks, TPB>>>(anchor, pos, neg, M, numNeg, out);
}